// round 15
// baseline (speedup 1.0000x reference)
#include <cuda_runtime.h>

// DeChunkLayer: B=4, L=4096, D=1024, fp32 in/out.
// h_t = (1-p_s[t]) h_{t-1} + p_s[t]*hidden[b,t,:];  out[b,l,:] = h_{plug[b,l]}.
// Pipeline: setup / chunk-local scan (Hs per rank) / warp-affine carry /
// dense gather-broadcast: out[l] = Hs[t] + P[t]*carry[t/CT], t = plug[l].

#define EPS_F 1e-4f

static constexpr int B = 4;
static constexpr int L = 4096;
static constexpr int D = 1024;
static constexpr int D4 = D / 4;
static constexpr int CT = 16;                 // ranks per chunk
static constexpr int NCHUNK = L / CT;         // 256 (worst case Nb = L)
static constexpr int CPL = NCHUNK / 32;       // 8 chunks per lane in carry scan
static constexpr int Z = 4;                   // D slices per chunk-scan block
static constexpr int TPZ = D4 / Z;            // 64 threads per slice block
static constexpr int ROWS = 4;                // output rows per bcast block

// Scratch (static device globals)
__device__ float g_Hs[B][L][D];               // chunk-local scan value per rank
__device__ float g_carry[B][NCHUNK][D];       // carry entering each chunk
__device__ float g_ps[B][L];                  // compacted clipped p by rank
__device__ float g_P[B][L];                   // within-chunk inclusive decay prod
__device__ int   g_plug[B][L];                // cumsum(mask)-1 per token
__device__ int   g_Nb[B];                     // boundary count per batch

// ---------------------------------------------------------------------------
// K1: prefix sum of mask; compact clipped p; plug indices; decay products.
// ---------------------------------------------------------------------------
__global__ __launch_bounds__(1024) void k_setup(const float* __restrict__ bp,
                                                const void* __restrict__ mask) {
    const int b = blockIdx.x;
    const int tid = threadIdx.x;              // 0..1023, 4 tokens each
    const int lane = tid & 31, warp = tid >> 5;

    __shared__ float s_ps[L];                 // 16 KB compacted p
    __shared__ int warp_sums[32];
    __shared__ int sNb;

    // ---- mask format detection (first 4096 words, in-bounds for all layouts)
    const unsigned int* mw = reinterpret_cast<const unsigned int*>(mask);
    int anyFloat = 0, nonBinary = 0;
    for (int i = tid; i < 4096; i += 1024) {
        unsigned int w = mw[i];
        anyFloat  |= (w == 0x3F800000u);
        nonBinary |= (w > 1u);
    }
    int haveFloat  = __syncthreads_or(anyFloat);
    int haveNonBin = __syncthreads_or(nonBinary);
    const int fmt = haveFloat ? 2 : (haveNonBin ? 0 : 1);  // 2=f32, 1=i32, 0=u8

    int cnt[4];
    if (fmt == 0) {
        uchar4 m4 = reinterpret_cast<const uchar4*>(mask)[b * 1024 + tid];
        cnt[0] = m4.x != 0; cnt[1] = m4.y != 0; cnt[2] = m4.z != 0; cnt[3] = m4.w != 0;
    } else {
        uint4 m4 = reinterpret_cast<const uint4*>(mask)[b * 1024 + tid];
        cnt[0] = m4.x != 0; cnt[1] = m4.y != 0; cnt[2] = m4.z != 0; cnt[3] = m4.w != 0;
    }
    int s = cnt[0] + cnt[1] + cnt[2] + cnt[3];

    int incl = s;
#pragma unroll
    for (int o = 1; o < 32; o <<= 1) {
        int v = __shfl_up_sync(0xffffffffu, incl, o);
        if (lane >= o) incl += v;
    }
    if (lane == 31) warp_sums[warp] = incl;
    __syncthreads();
    if (warp == 0) {
        int ws = warp_sums[lane];
#pragma unroll
        for (int o = 1; o < 32; o <<= 1) {
            int v = __shfl_up_sync(0xffffffffu, ws, o);
            if (lane >= o) ws += v;
        }
        warp_sums[lane] = ws;
    }
    __syncthreads();
    int warp_excl = (warp == 0) ? 0 : warp_sums[warp - 1];
    int run = warp_excl + (incl - s);

    const int base = tid * 4;
#pragma unroll
    for (int k = 0; k < 4; ++k) {
        run += cnt[k];
        int l = base + k;
        g_plug[b][l] = run - 1;
        if (cnt[k]) {
            float p = bp[(b * L + l) * 2 + 1];
            p = fminf(fmaxf(p, EPS_F), 1.0f - EPS_F);
            int t = run - 1;
            g_ps[b][t] = p;
            s_ps[t]    = p;
        }
    }
    if (tid == 1023) { g_Nb[b] = run; sNb = run; }
    __syncthreads();

    const int Nb = sNb;
    // within-chunk inclusive decay products (NCHUNK threads x CT smem reads)
    if (tid < NCHUNK) {
        const int t0 = tid * CT;
        if (t0 < Nb) {
            float prod = 1.0f;
#pragma unroll
            for (int j = 0; j < CT; ++j) {
                int t = t0 + j;
                bool valid = (t < Nb);
                prod *= (1.0f - (valid ? s_ps[t] : 0.0f));
                if (valid) g_P[b][t] = prod;
            }
        }
    }
}

// ---------------------------------------------------------------------------
// K2: chunk-local scan (carry-in 0); write every h_t to Hs. D-sliced,
// branchless (p=0 identity pad), all CT x-loads preloaded (MLP=16).
// ---------------------------------------------------------------------------
__global__ __launch_bounds__(TPZ) void k_chunkscan(const float* __restrict__ hidden) {
    const int b = blockIdx.y;
    const int c = blockIdx.x;
    const int z = blockIdx.z;
    const int Nb = g_Nb[b];
    const int t0 = c * CT;
    if (t0 >= Nb) return;

    __shared__ float s_p[CT];
    if (threadIdx.x < CT) {
        int t = t0 + threadIdx.x;
        s_p[threadIdx.x] = (t < Nb) ? g_ps[b][t] : 0.0f;   // identity pad
    }
    __syncthreads();

    const int d4 = z * TPZ + threadIdx.x;
    const float4* hid = reinterpret_cast<const float4*>(hidden + b * L * D) + d4;
    float4* Hs = reinterpret_cast<float4*>(&g_Hs[b][0][0]) + d4;

    float4 xr[CT];
#pragma unroll
    for (int j = 0; j < CT; ++j) xr[j] = hid[(t0 + j) * D4];

    float4 h = make_float4(0.f, 0.f, 0.f, 0.f);
#pragma unroll
    for (int j = 0; j < CT; ++j) {
        float p = s_p[j];
        float dec = 1.0f - p;
        h.x = fmaf(dec, h.x, p * xr[j].x);
        h.y = fmaf(dec, h.y, p * xr[j].y);
        h.z = fmaf(dec, h.z, p * xr[j].z);
        h.w = fmaf(dec, h.w, p * xr[j].w);
        Hs[(t0 + j) * D4] = h;
    }
}

// ---------------------------------------------------------------------------
// K3: carry across chunks. Warp per (b,d); 8 chunks per lane, affine
// compose + 5-step shuffle scan. Dead chunks are identity (A=1, U=0).
// ---------------------------------------------------------------------------
__global__ __launch_bounds__(256) void k_carry() {
    const int warp = threadIdx.x >> 5;
    const int lane = threadIdx.x & 31;
    const int g = blockIdx.x * 8 + warp;      // 0..4095 = (b,d)
    const int b = g >> 10;
    const int d = g & 1023;
    const int Nb = g_Nb[b];

    float a[CPL], u[CPL];
    float A = 1.0f, U = 0.0f;
#pragma unroll
    for (int k = 0; k < CPL; ++k) {
        const int c = CPL * lane + k;
        const int t0 = c * CT;
        if (t0 < Nb) {
            int endt = min(t0 + CT, Nb) - 1;
            a[k] = g_P[b][endt];
            u[k] = g_Hs[b][endt][d];          // chunk-end local value
        } else {
            a[k] = 1.0f; u[k] = 0.0f;
        }
        U = fmaf(a[k], U, u[k]);
        A *= a[k];
    }

    // inclusive warp scan with affine composition
#pragma unroll
    for (int o = 1; o < 32; o <<= 1) {
        float pa = __shfl_up_sync(0xffffffffu, A, o);
        float pu = __shfl_up_sync(0xffffffffu, U, o);
        if (lane >= o) {
            U = fmaf(A, pu, U);
            A = A * pa;
        }
    }
    // exclusive prefix entering this lane's first chunk
    float s = __shfl_up_sync(0xffffffffu, U, 1);
    if (lane == 0) s = 0.0f;

#pragma unroll
    for (int k = 0; k < CPL; ++k) {
        const int c = CPL * lane + k;
        g_carry[b][c][d] = s;
        s = fmaf(a[k], s, u[k]);
    }
}

// ---------------------------------------------------------------------------
// K4: dense gather-broadcast. Block = 4 consecutive output rows x 256 thr.
// out[b,l,:] = Hs[t] + P[t]*carry[t>>4], t = plug[b][l]. Gathers are L1/L2
// hot (consecutive rows share t); all 8 loads per thread independent.
// ---------------------------------------------------------------------------
__global__ __launch_bounds__(256) void k_bcast(float* __restrict__ out) {
    const int blk = blockIdx.x;               // B*L/ROWS blocks
    const int b = blk >> 10;                  // (L/ROWS)=1024 blocks per batch
    const int l0 = (blk & 1023) * ROWS;
    const int d4 = threadIdx.x;

    __shared__ int s_t[ROWS];
    if (threadIdx.x < ROWS) s_t[threadIdx.x] = g_plug[b][l0 + threadIdx.x];
    __syncthreads();

    float4 o[ROWS];
#pragma unroll
    for (int i = 0; i < ROWS; ++i) {
        const int t = s_t[i];
        float4 hl = __ldg(reinterpret_cast<const float4*>(&g_Hs[b][t][0]) + d4);
        float4 cy = __ldg(reinterpret_cast<const float4*>(&g_carry[b][t >> 4][0]) + d4);
        float Pv = __ldg(&g_P[b][t]);
        o[i].x = fmaf(Pv, cy.x, hl.x);
        o[i].y = fmaf(Pv, cy.y, hl.y);
        o[i].z = fmaf(Pv, cy.z, hl.z);
        o[i].w = fmaf(Pv, cy.w, hl.w);
    }

    float4* dst = reinterpret_cast<float4*>(out) + ((b << 12) + l0) * D4 + d4;
#pragma unroll
    for (int i = 0; i < ROWS; ++i) dst[i * D4] = o[i];
}

// ---------------------------------------------------------------------------
extern "C" void kernel_launch(void* const* d_in, const int* in_sizes, int n_in,
                              void* d_out, int out_size) {
    const float* hidden = nullptr;
    const float* bp = nullptr;
    const void* mask = nullptr;
    for (int i = 0; i < n_in; ++i) {
        if (in_sizes[i] == B * L * D)      hidden = (const float*)d_in[i];
        else if (in_sizes[i] == B * L * 2) bp = (const float*)d_in[i];
        else if (in_sizes[i] == B * L)     mask = d_in[i];
    }
    float* out = (float*)d_out;

    k_setup<<<B, 1024>>>(bp, mask);
    k_chunkscan<<<dim3(NCHUNK, B, Z), TPZ>>>(hidden);
    k_carry<<<B * D / 8, 256>>>();
    k_bcast<<<B * L / ROWS, 256>>>(out);
}